// round 10
// baseline (speedup 1.0000x reference)
#include <cuda_runtime.h>
#include <cstdint>

#define N_NODES 50000
#define N_EDGES 800000
#define D 64
#define N_LAYERS 3

// Scratch (allocation-free rule: __device__ globals). float4 => 16B aligned.
// g_cnt: zero-initialized at module load; reorder_kernel re-zeroes it each
// call, so every kernel_launch sees cnt == 0 (deterministic).
__device__ float4 g_buf0[N_NODES * D / 4];
__device__ float4 g_buf1[N_NODES * D / 4];
__device__ int    g_cnt   [N_NODES];
__device__ int    g_rowptr[N_NODES + 1];
__device__ int    g_cursor[N_NODES];
__device__ int    g_col   [N_EDGES];

// ---------------------------------------------------------------------------
// f32x2 packed-math helpers (sm_103a)
// ---------------------------------------------------------------------------
__device__ __forceinline__ unsigned long long fma2(unsigned long long a,
                                                   unsigned long long b,
                                                   unsigned long long c) {
    unsigned long long d;
    asm("fma.rn.f32x2 %0, %1, %2, %3;" : "=l"(d) : "l"(a), "l"(b), "l"(c));
    return d;
}
__device__ __forceinline__ unsigned long long bcast2(float x) {
    unsigned long long d;
    unsigned int xi = __float_as_uint(x);
    asm("mov.b64 %0, {%1, %1};" : "=l"(d) : "r"(xi));
    return d;
}
__device__ __forceinline__ float2 unpack2(unsigned long long v) {
    unsigned int lo, hi;
    asm("mov.b64 {%0, %1}, %2;" : "=r"(lo), "=r"(hi) : "l"(v));
    return make_float2(__uint_as_float(lo), __uint_as_float(hi));
}

// ---------------------------------------------------------------------------
// idx 0: in-degree histogram (cnt must be 0 on entry)
// ---------------------------------------------------------------------------
__global__ void hist_kernel(const int* __restrict__ dst, int* __restrict__ cnt) {
    int e = blockIdx.x * blockDim.x + threadIdx.x;
    if (e < N_EDGES) atomicAdd(&cnt[dst[e]], 1);
}

// ---------------------------------------------------------------------------
// idx 1: exclusive prefix sum (single block, 1024 threads) — proven version
// ---------------------------------------------------------------------------
#define SCAN_THREADS 1024
#define CHUNK ((N_NODES + SCAN_THREADS - 1) / SCAN_THREADS)   // 49

__global__ void __launch_bounds__(SCAN_THREADS) scan_kernel(
        const int* __restrict__ cnt,
        int* __restrict__ rowptr,
        int* __restrict__ cursor) {
    __shared__ int s[SCAN_THREADS];
    const int t = threadIdx.x;
    const int base = t * CHUNK;

    int total = 0;
    #pragma unroll 7
    for (int i = 0; i < CHUNK; i++) {
        int idx = base + i;
        if (idx < N_NODES) total += cnt[idx];
    }
    s[t] = total;
    __syncthreads();

    #pragma unroll
    for (int off = 1; off < SCAN_THREADS; off <<= 1) {
        int v = (t >= off) ? s[t - off] : 0;
        __syncthreads();
        s[t] += v;
        __syncthreads();
    }
    int run = (t == 0) ? 0 : s[t - 1];

    #pragma unroll 7
    for (int i = 0; i < CHUNK; i++) {
        int idx = base + i;
        if (idx < N_NODES) {
            rowptr[idx] = run;
            cursor[idx] = run;
            run += cnt[idx];
        }
    }
    if (t == 0) rowptr[N_NODES] = N_EDGES;
}

// ---------------------------------------------------------------------------
// idx 2: reorder; also re-zeroes cnt for the next call
// ---------------------------------------------------------------------------
__global__ void reorder_kernel(const int* __restrict__ src,
                               const int* __restrict__ dst,
                               int* __restrict__ cursor,
                               int* __restrict__ col,
                               int* __restrict__ cnt) {
    int e = blockIdx.x * blockDim.x + threadIdx.x;
    if (e < N_NODES) cnt[e] = 0;
    if (e >= N_EDGES) return;
    int p = atomicAdd(&cursor[dst[e]], 1);
    col[p] = src[e];
}

// ---------------------------------------------------------------------------
// idx 3 (layer 0, ncu slot): FUSED gather + dual-GEMM node update.
// out = relu?( x @ Wself + (sum_{e in in(n)} x[col[e]]) @ Wmsg + b )
// 128-row tile, 512 threads.
// Phase 1 (gather): 4 threads per node; thread q owns float4s [q*4, q*4+4)
//   of the node row. Exclusive slices -> register accumulate -> sA. No atomics.
// Phase 2 (gemm): warp w -> cols (w&7)*8..+8, row half (w>>3)*64;
//   lane l -> rows rh+l, rh+l+32. Weight LDS full-warp broadcast; f32x2 FMA.
// ---------------------------------------------------------------------------
#define TILE_ROWS 128
#define XSTRIDE 68
#define SMEM_FLOATS (2 * 64 * 64 + 2 * TILE_ROWS * XSTRIDE)

__global__ void __launch_bounds__(512) fused_gemm_kernel(
        const float* __restrict__ x,
        const int* __restrict__ rowptr,
        const int* __restrict__ col,
        const float* __restrict__ Wself,
        const float* __restrict__ Wmsg,
        const float* __restrict__ bias,
        float* __restrict__ out,
        int apply_relu) {
    extern __shared__ float sm[];
    float* sWs = sm;                          // [64][64]
    float* sWm = sm + 64 * 64;                // [64][64]
    float* sX  = sm + 2 * 64 * 64;            // [TILE_ROWS][XSTRIDE]
    float* sA  = sX + TILE_ROWS * XSTRIDE;    // [TILE_ROWS][XSTRIDE]

    const int tid     = threadIdx.x;
    const int rowbase = blockIdx.x * TILE_ROWS;
    const float4* x4  = reinterpret_cast<const float4*>(x);

    // ---- weight + x tile fills ----
    for (int i = tid; i < 64 * 64 / 4; i += 512) {
        reinterpret_cast<float4*>(sWs)[i] = reinterpret_cast<const float4*>(Wself)[i];
        reinterpret_cast<float4*>(sWm)[i] = reinterpret_cast<const float4*>(Wmsg)[i];
    }
    for (int i = tid; i < TILE_ROWS * 16; i += 512) {
        int r = i >> 4;
        int c = i & 15;
        int grow = rowbase + r;
        float4 vx = make_float4(0.f, 0.f, 0.f, 0.f);
        if (grow < N_NODES)
            vx = x4[(size_t)grow * 16 + c];
        *reinterpret_cast<float4*>(sX + r * XSTRIDE + c * 4) = vx;
    }

    // ---- Phase 1: gather-sum in-edges into sA ----
    {
        const int r = tid >> 2;        // local node row 0..127
        const int q = tid & 3;         // float4 group: owns [q*4, q*4+4)
        const int n = rowbase + r;

        float4 a0 = make_float4(0.f, 0.f, 0.f, 0.f);
        float4 a1 = a0, a2 = a0, a3 = a0;

        if (n < N_NODES) {
            const int beg = rowptr[n];
            const int end = rowptr[n + 1];
            int e = beg;
            for (; e + 2 <= end; e += 2) {
                const float4* p0 = x4 + (size_t)col[e]     * 16 + q * 4;
                const float4* p1 = x4 + (size_t)col[e + 1] * 16 + q * 4;
                float4 u0 = __ldg(p0), u1 = __ldg(p0 + 1);
                float4 u2 = __ldg(p0 + 2), u3 = __ldg(p0 + 3);
                float4 w0 = __ldg(p1), w1 = __ldg(p1 + 1);
                float4 w2 = __ldg(p1 + 2), w3 = __ldg(p1 + 3);
                a0.x += u0.x + w0.x; a0.y += u0.y + w0.y;
                a0.z += u0.z + w0.z; a0.w += u0.w + w0.w;
                a1.x += u1.x + w1.x; a1.y += u1.y + w1.y;
                a1.z += u1.z + w1.z; a1.w += u1.w + w1.w;
                a2.x += u2.x + w2.x; a2.y += u2.y + w2.y;
                a2.z += u2.z + w2.z; a2.w += u2.w + w2.w;
                a3.x += u3.x + w3.x; a3.y += u3.y + w3.y;
                a3.z += u3.z + w3.z; a3.w += u3.w + w3.w;
            }
            if (e < end) {
                const float4* p = x4 + (size_t)col[e] * 16 + q * 4;
                float4 u0 = __ldg(p), u1 = __ldg(p + 1);
                float4 u2 = __ldg(p + 2), u3 = __ldg(p + 3);
                a0.x += u0.x; a0.y += u0.y; a0.z += u0.z; a0.w += u0.w;
                a1.x += u1.x; a1.y += u1.y; a1.z += u1.z; a1.w += u1.w;
                a2.x += u2.x; a2.y += u2.y; a2.z += u2.z; a2.w += u2.w;
                a3.x += u3.x; a3.y += u3.y; a3.z += u3.z; a3.w += u3.w;
            }
        }
        float* dst = sA + r * XSTRIDE + q * 16;
        *reinterpret_cast<float4*>(dst)      = a0;
        *reinterpret_cast<float4*>(dst + 4)  = a1;
        *reinterpret_cast<float4*>(dst + 8)  = a2;
        *reinterpret_cast<float4*>(dst + 12) = a3;
    }
    __syncthreads();

    // ---- Phase 2: dual GEMM ----
    const int w  = tid >> 5;
    const int l  = tid & 31;
    const int cb = (w & 7) * 8;           // column base
    const int rh = (w >> 3) * 64;         // row half base

    const float* xr0 = sX + (rh + l) * XSTRIDE;
    const float* xr1 = sX + (rh + l + 32) * XSTRIDE;
    const float* ar0 = sA + (rh + l) * XSTRIDE;
    const float* ar1 = sA + (rh + l + 32) * XSTRIDE;

    unsigned long long acc[8];
    {
        ulonglong2 b0 = *reinterpret_cast<const ulonglong2*>(bias + cb);
        ulonglong2 b1 = *reinterpret_cast<const ulonglong2*>(bias + cb + 4);
        acc[0] = b0.x; acc[1] = b0.y; acc[2] = b1.x; acc[3] = b1.y;
        acc[4] = b0.x; acc[5] = b0.y; acc[6] = b1.x; acc[7] = b1.y;
    }

    #pragma unroll 4
    for (int k4 = 0; k4 < 64; k4 += 4) {
        float4 xv0 = *reinterpret_cast<const float4*>(xr0 + k4);
        float4 xv1 = *reinterpret_cast<const float4*>(xr1 + k4);
        float4 av0 = *reinterpret_cast<const float4*>(ar0 + k4);
        float4 av1 = *reinterpret_cast<const float4*>(ar1 + k4);
        const float xs0[4] = { xv0.x, xv0.y, xv0.z, xv0.w };
        const float xs1[4] = { xv1.x, xv1.y, xv1.z, xv1.w };
        const float as0[4] = { av0.x, av0.y, av0.z, av0.w };
        const float as1[4] = { av1.x, av1.y, av1.z, av1.w };
        #pragma unroll
        for (int kk = 0; kk < 4; kk++) {
            const int k = k4 + kk;
            const float* wsk = sWs + k * 64 + cb;
            const float* wmk = sWm + k * 64 + cb;
            ulonglong2 wsl = *reinterpret_cast<const ulonglong2*>(wsk);
            ulonglong2 wsh = *reinterpret_cast<const ulonglong2*>(wsk + 4);
            ulonglong2 wml = *reinterpret_cast<const ulonglong2*>(wmk);
            ulonglong2 wmh = *reinterpret_cast<const ulonglong2*>(wmk + 4);

            unsigned long long x0b = bcast2(xs0[kk]);
            unsigned long long x1b = bcast2(xs1[kk]);
            unsigned long long a0b = bcast2(as0[kk]);
            unsigned long long a1b = bcast2(as1[kk]);

            acc[0] = fma2(x0b, wsl.x, acc[0]);
            acc[1] = fma2(x0b, wsl.y, acc[1]);
            acc[2] = fma2(x0b, wsh.x, acc[2]);
            acc[3] = fma2(x0b, wsh.y, acc[3]);
            acc[0] = fma2(a0b, wml.x, acc[0]);
            acc[1] = fma2(a0b, wml.y, acc[1]);
            acc[2] = fma2(a0b, wmh.x, acc[2]);
            acc[3] = fma2(a0b, wmh.y, acc[3]);

            acc[4] = fma2(x1b, wsl.x, acc[4]);
            acc[5] = fma2(x1b, wsl.y, acc[5]);
            acc[6] = fma2(x1b, wsh.x, acc[6]);
            acc[7] = fma2(x1b, wsh.y, acc[7]);
            acc[4] = fma2(a1b, wml.x, acc[4]);
            acc[5] = fma2(a1b, wml.y, acc[5]);
            acc[6] = fma2(a1b, wmh.x, acc[6]);
            acc[7] = fma2(a1b, wmh.y, acc[7]);
        }
    }

    #pragma unroll
    for (int rr = 0; rr < 2; rr++) {
        const int grow = rowbase + rh + l + rr * 32;
        if (grow < N_NODES) {
            float* op = out + (size_t)grow * D + cb;
            float2 p0 = unpack2(acc[rr * 4 + 0]);
            float2 p1 = unpack2(acc[rr * 4 + 1]);
            float2 p2 = unpack2(acc[rr * 4 + 2]);
            float2 p3 = unpack2(acc[rr * 4 + 3]);
            float4 v0 = make_float4(p0.x, p0.y, p1.x, p1.y);
            float4 v1 = make_float4(p2.x, p2.y, p3.x, p3.y);
            if (apply_relu) {
                v0.x = fmaxf(v0.x, 0.f); v0.y = fmaxf(v0.y, 0.f);
                v0.z = fmaxf(v0.z, 0.f); v0.w = fmaxf(v0.w, 0.f);
                v1.x = fmaxf(v1.x, 0.f); v1.y = fmaxf(v1.y, 0.f);
                v1.z = fmaxf(v1.z, 0.f); v1.w = fmaxf(v1.w, 0.f);
            }
            *reinterpret_cast<float4*>(op)     = v0;
            *reinterpret_cast<float4*>(op + 4) = v1;
        }
    }
}

// ---------------------------------------------------------------------------
// Launch: hist(0), scan(1), reorder(2), fused_gemm(3 <- ncu), fused, fused.
// ---------------------------------------------------------------------------
extern "C" void kernel_launch(void* const* d_in, const int* in_sizes, int n_in,
                              void* d_out, int out_size) {
    (void)in_sizes; (void)n_in; (void)out_size;

    const float* x0    = (const float*)d_in[0];
    const int*   ei    = (const int*)d_in[1];      // int32 (JAX x64 disabled)
    const float* Wmsg  = (const float*)d_in[2];    // [3][64][64]
    const float* Wself = (const float*)d_in[3];    // [3][64][64]
    const float* bias  = (const float*)d_in[4];    // [3][64]
    float*       out   = (float*)d_out;

    const int* src = ei;
    const int* dst = ei + N_EDGES;

    float4 *buf0, *buf1;
    int *cnt, *rowptr, *cursor, *col;
    cudaGetSymbolAddress((void**)&buf0,   g_buf0);
    cudaGetSymbolAddress((void**)&buf1,   g_buf1);
    cudaGetSymbolAddress((void**)&cnt,    g_cnt);
    cudaGetSymbolAddress((void**)&rowptr, g_rowptr);
    cudaGetSymbolAddress((void**)&cursor, g_cursor);
    cudaGetSymbolAddress((void**)&col,    g_col);

    static bool attr_set = false;
    const int smem_bytes = SMEM_FLOATS * (int)sizeof(float);
    if (!attr_set) {
        cudaFuncSetAttribute(fused_gemm_kernel,
                             cudaFuncAttributeMaxDynamicSharedMemorySize, smem_bytes);
        attr_set = true;
    }

    // ---- CSR build (proven 3-kernel version) ----
    hist_kernel<<<(N_EDGES + 255) / 256, 256>>>(dst, cnt);                      // 0
    scan_kernel<<<1, SCAN_THREADS>>>(cnt, rowptr, cursor);                      // 1
    reorder_kernel<<<(N_EDGES + 255) / 256, 256>>>(src, dst, cursor, col, cnt); // 2

    // ---- Layers (one fused kernel each) ----
    const float* cur[N_LAYERS]  = { x0, (const float*)buf0, (const float*)buf1 };
    float*       next[N_LAYERS] = { (float*)buf0, (float*)buf1, out };

    const int gemm_blocks = (N_NODES + TILE_ROWS - 1) / TILE_ROWS;  // 391

    for (int layer = 0; layer < N_LAYERS; layer++) {
        fused_gemm_kernel<<<gemm_blocks, 512, smem_bytes>>>(   // 3,4,5 (3 <- ncu)
            cur[layer], rowptr, col,
            Wself + (size_t)layer * D * D,
            Wmsg  + (size_t)layer * D * D,
            bias  + (size_t)layer * D,
            next[layer],
            layer < N_LAYERS - 1 ? 1 : 0);
    }
}

// round 14
// speedup vs baseline: 1.3112x; 1.3112x over previous
#include <cuda_runtime.h>
#include <cstdint>

#define N_NODES 50000
#define N_EDGES 800000
#define D 64
#define N_LAYERS 3

// Scratch (allocation-free rule: __device__ globals). float4 => 16B aligned.
// g_cnt: zero-initialized at module load; reorder_kernel re-zeroes it each
// call, so every kernel_launch sees cnt == 0 (deterministic).
__device__ float4 g_buf0[N_NODES * D / 4];
__device__ float4 g_buf1[N_NODES * D / 4];
__device__ float4 g_agg [N_NODES * D / 4];
__device__ int    g_cnt   [N_NODES];
__device__ int    g_rowptr[N_NODES + 1];
__device__ int    g_cursor[N_NODES];
__device__ int    g_col   [N_EDGES];

// ---------------------------------------------------------------------------
// tf32 helpers
// ---------------------------------------------------------------------------
__device__ __forceinline__ unsigned f2tf32(float f) {
    unsigned r;
    asm("cvt.rna.tf32.f32 %0, %1;" : "=r"(r) : "f"(f));
    return r;
}
// split v into hi (tf32 bits, also valid fp32) and lo (tf32 of remainder)
__device__ __forceinline__ void tf32_split(float v, unsigned& hi, unsigned& lo) {
    hi = f2tf32(v);
    float rem = v - __uint_as_float(hi);
    lo = f2tf32(rem);
}
// D = A(16x8,tf32) * B(8x8,tf32) + D, fp32 accum
__device__ __forceinline__ void mma_tf32(float c[4], const unsigned a[4],
                                         const unsigned b[2]) {
    asm volatile(
        "mma.sync.aligned.m16n8k8.row.col.f32.tf32.tf32.f32 "
        "{%0,%1,%2,%3}, {%4,%5,%6,%7}, {%8,%9}, {%0,%1,%2,%3};\n"
        : "+f"(c[0]), "+f"(c[1]), "+f"(c[2]), "+f"(c[3])
        : "r"(a[0]), "r"(a[1]), "r"(a[2]), "r"(a[3]), "r"(b[0]), "r"(b[1]));
}

// ---------------------------------------------------------------------------
// idx 0: in-degree histogram (cnt must be 0 on entry)
// ---------------------------------------------------------------------------
__global__ void hist_kernel(const int* __restrict__ dst, int* __restrict__ cnt) {
    int e = blockIdx.x * blockDim.x + threadIdx.x;
    if (e < N_EDGES) atomicAdd(&cnt[dst[e]], 1);
}

// ---------------------------------------------------------------------------
// idx 1: exclusive prefix sum (single block, 1024 threads)
// ---------------------------------------------------------------------------
#define SCAN_THREADS 1024
#define CHUNK ((N_NODES + SCAN_THREADS - 1) / SCAN_THREADS)   // 49

__global__ void __launch_bounds__(SCAN_THREADS) scan_kernel(
        const int* __restrict__ cnt,
        int* __restrict__ rowptr,
        int* __restrict__ cursor) {
    __shared__ int s[SCAN_THREADS];
    const int t = threadIdx.x;
    const int base = t * CHUNK;

    int total = 0;
    #pragma unroll 7
    for (int i = 0; i < CHUNK; i++) {
        int idx = base + i;
        if (idx < N_NODES) total += cnt[idx];
    }
    s[t] = total;
    __syncthreads();

    #pragma unroll
    for (int off = 1; off < SCAN_THREADS; off <<= 1) {
        int v = (t >= off) ? s[t - off] : 0;
        __syncthreads();
        s[t] += v;
        __syncthreads();
    }
    int run = (t == 0) ? 0 : s[t - 1];

    #pragma unroll 7
    for (int i = 0; i < CHUNK; i++) {
        int idx = base + i;
        if (idx < N_NODES) {
            rowptr[idx] = run;
            cursor[idx] = run;
            run += cnt[idx];
        }
    }
    if (t == 0) rowptr[N_NODES] = N_EDGES;
}

// ---------------------------------------------------------------------------
// idx 2: reorder; also re-zeroes cnt for the next call
// ---------------------------------------------------------------------------
__global__ void reorder_kernel(const int* __restrict__ src,
                               const int* __restrict__ dst,
                               int* __restrict__ cursor,
                               int* __restrict__ col,
                               int* __restrict__ cnt) {
    int e = blockIdx.x * blockDim.x + threadIdx.x;
    if (e < N_NODES) cnt[e] = 0;
    if (e >= N_EDGES) return;
    int p = atomicAdd(&cursor[dst[e]], 1);
    col[p] = src[e];
}

// ---------------------------------------------------------------------------
// idx 3 (layer 0, ncu slot): agg[n] = sum_{e in in(n)} x[col[e]]  (21 us)
// ---------------------------------------------------------------------------
__global__ void __launch_bounds__(256) agg_kernel(
        const float4* __restrict__ x4,
        const int* __restrict__ rowptr,
        const int* __restrict__ col,
        float4* __restrict__ agg4) {
    const int n    = blockIdx.x * 32 + (threadIdx.x >> 3);
    const int lane = threadIdx.x & 7;
    if (n >= N_NODES) return;
    const int beg = rowptr[n];
    const int end = rowptr[n + 1];

    float4 a0 = make_float4(0.f, 0.f, 0.f, 0.f);
    float4 a1 = make_float4(0.f, 0.f, 0.f, 0.f);

    int e = beg;
    for (; e + 4 <= end; e += 4) {
        int s0 = col[e], s1 = col[e + 1], s2 = col[e + 2], s3 = col[e + 3];
        const float4* p0 = x4 + (size_t)s0 * 16 + lane;
        const float4* p1 = x4 + (size_t)s1 * 16 + lane;
        const float4* p2 = x4 + (size_t)s2 * 16 + lane;
        const float4* p3 = x4 + (size_t)s3 * 16 + lane;
        float4 v00 = __ldg(p0),     v01 = __ldg(p0 + 8);
        float4 v10 = __ldg(p1),     v11 = __ldg(p1 + 8);
        float4 v20 = __ldg(p2),     v21 = __ldg(p2 + 8);
        float4 v30 = __ldg(p3),     v31 = __ldg(p3 + 8);
        a0.x += v00.x + v10.x + v20.x + v30.x;
        a0.y += v00.y + v10.y + v20.y + v30.y;
        a0.z += v00.z + v10.z + v20.z + v30.z;
        a0.w += v00.w + v10.w + v20.w + v30.w;
        a1.x += v01.x + v11.x + v21.x + v31.x;
        a1.y += v01.y + v11.y + v21.y + v31.y;
        a1.z += v01.z + v11.z + v21.z + v31.z;
        a1.w += v01.w + v11.w + v21.w + v31.w;
    }
    for (; e < end; e++) {
        const float4* p = x4 + (size_t)col[e] * 16 + lane;
        float4 v0 = __ldg(p), v1 = __ldg(p + 8);
        a0.x += v0.x; a0.y += v0.y; a0.z += v0.z; a0.w += v0.w;
        a1.x += v1.x; a1.y += v1.y; a1.z += v1.z; a1.w += v1.w;
    }
    agg4[(size_t)n * 16 + lane]     = a0;
    agg4[(size_t)n * 16 + 8 + lane] = a1;
}

// ---------------------------------------------------------------------------
// Tensor-core node update: out = relu?( x @ Wself + agg @ Wmsg + b )
// 3xTF32 mma.sync.m16n8k8. Block 256 thr / 8 warps, tile 128(M) x 64(N).
// Warp grid 4(M) x 2(N): warp covers 32x32 = 2 m-tiles x 4 n-tiles.
// smem strides of 68 floats make all fragment LDS bank-conflict-free:
// bank = (4*g + tid4 + const) covers all 32 banks.
// Weights stored transposed: sWt[n][k].
// ---------------------------------------------------------------------------
#define TILE_ROWS 128
#define XSTRIDE 68
#define WSTRIDE 68
#define SMEM_FLOATS (2 * TILE_ROWS * XSTRIDE + 2 * 64 * WSTRIDE)

__global__ void __launch_bounds__(256) node_gemm_tc_kernel(
        const float* __restrict__ x,
        const float* __restrict__ agg,
        const float* __restrict__ Wself,
        const float* __restrict__ Wmsg,
        const float* __restrict__ bias,
        float* __restrict__ out,
        int apply_relu) {
    extern __shared__ float sm[];
    float* sX   = sm;                             // [128][68]
    float* sA   = sX + TILE_ROWS * XSTRIDE;       // [128][68]
    float* sWsT = sA + TILE_ROWS * XSTRIDE;       // [64][68]  Wself^T (n-major)
    float* sWmT = sWsT + 64 * WSTRIDE;            // [64][68]  Wmsg^T

    const int tid     = threadIdx.x;
    const int rowbase = blockIdx.x * TILE_ROWS;
    const float4* x4  = reinterpret_cast<const float4*>(x);
    const float4* a4  = reinterpret_cast<const float4*>(agg);

    // ---- fill x / agg tiles (float4, stride 68) ----
    for (int i = tid; i < TILE_ROWS * 16; i += 256) {
        int r = i >> 4;
        int c = i & 15;
        int grow = rowbase + r;
        float4 vx = make_float4(0.f, 0.f, 0.f, 0.f);
        float4 va = vx;
        if (grow < N_NODES) {
            vx = x4[(size_t)grow * 16 + c];
            va = a4[(size_t)grow * 16 + c];
        }
        *reinterpret_cast<float4*>(sX + r * XSTRIDE + c * 4) = vx;
        *reinterpret_cast<float4*>(sA + r * XSTRIDE + c * 4) = va;
    }
    // ---- fill transposed weights: sWt[n][k] = W[k][n] ----
    for (int i = tid; i < 64 * 64; i += 256) {
        int k = i >> 6;
        int n = i & 63;
        sWsT[n * WSTRIDE + k] = Wself[k * 64 + n];
        sWmT[n * WSTRIDE + k] = Wmsg [k * 64 + n];
    }
    __syncthreads();

    const int w      = tid >> 5;
    const int lane   = tid & 31;
    const int g      = lane >> 2;     // groupID (0..7)
    const int tid4   = lane & 3;      // threadID_in_group (0..3)
    const int warp_m = w >> 1;        // 0..3 -> row block warp_m*32
    const int warp_n = w & 1;         // 0..1 -> col block warp_n*32

    // C accumulators: 2 m-tiles x 4 n-tiles, 4 regs each
    float cacc[8][4];
    #pragma unroll
    for (int i = 0; i < 8; i++)
        #pragma unroll
        for (int j = 0; j < 4; j++) cacc[i][j] = 0.f;

    // ---- two GEMMs accumulate into the same C: (sX,WsT) then (sA,WmT) ----
    #pragma unroll 1
    for (int part = 0; part < 2; part++) {
        const float* sM  = part ? sA   : sX;
        const float* sWt = part ? sWmT : sWsT;

        #pragma unroll
        for (int k0 = 0; k0 < 64; k0 += 8) {
            // A fragments (2 m-tiles), split hi/lo
            unsigned ah[2][4], al[2][4];
            #pragma unroll
            for (int mt = 0; mt < 2; mt++) {
                const int rb = warp_m * 32 + mt * 16;
                float v0 = sM[(rb + g)     * XSTRIDE + k0 + tid4];
                float v1 = sM[(rb + g + 8) * XSTRIDE + k0 + tid4];
                float v2 = sM[(rb + g)     * XSTRIDE + k0 + tid4 + 4];
                float v3 = sM[(rb + g + 8) * XSTRIDE + k0 + tid4 + 4];
                tf32_split(v0, ah[mt][0], al[mt][0]);
                tf32_split(v1, ah[mt][1], al[mt][1]);
                tf32_split(v2, ah[mt][2], al[mt][2]);
                tf32_split(v3, ah[mt][3], al[mt][3]);
            }
            // B fragments (4 n-tiles), split hi/lo. B[k][n] = sWt[n][k].
            unsigned bh[4][2], bl[4][2];
            #pragma unroll
            for (int nt = 0; nt < 4; nt++) {
                const int nc = warp_n * 32 + nt * 8 + g;
                float w0 = sWt[nc * WSTRIDE + k0 + tid4];
                float w1 = sWt[nc * WSTRIDE + k0 + tid4 + 4];
                tf32_split(w0, bh[nt][0], bl[nt][0]);
                tf32_split(w1, bh[nt][1], bl[nt][1]);
            }
            // 3xTF32: Ah*Bh + Al*Bh + Ah*Bl
            #pragma unroll
            for (int mt = 0; mt < 2; mt++)
                #pragma unroll
                for (int nt = 0; nt < 4; nt++) {
                    float* c = cacc[mt * 4 + nt];
                    mma_tf32(c, ah[mt], bh[nt]);
                    mma_tf32(c, al[mt], bh[nt]);
                    mma_tf32(c, ah[mt], bl[nt]);
                }
        }
    }

    // ---- epilogue: bias + relu + store ----
    #pragma unroll
    for (int mt = 0; mt < 2; mt++) {
        #pragma unroll
        for (int nt = 0; nt < 4; nt++) {
            const float* c = cacc[mt * 4 + nt];
            const int colb = warp_n * 32 + nt * 8 + tid4 * 2;
            const float2 bv = *reinterpret_cast<const float2*>(bias + colb);
            const int r0 = rowbase + warp_m * 32 + mt * 16 + g;
            const int r1 = r0 + 8;
            float2 v0 = make_float2(c[0] + bv.x, c[1] + bv.y);
            float2 v1 = make_float2(c[2] + bv.x, c[3] + bv.y);
            if (apply_relu) {
                v0.x = fmaxf(v0.x, 0.f); v0.y = fmaxf(v0.y, 0.f);
                v1.x = fmaxf(v1.x, 0.f); v1.y = fmaxf(v1.y, 0.f);
            }
            if (r0 < N_NODES)
                *reinterpret_cast<float2*>(out + (size_t)r0 * D + colb) = v0;
            if (r1 < N_NODES)
                *reinterpret_cast<float2*>(out + (size_t)r1 * D + colb) = v1;
        }
    }
}

// ---------------------------------------------------------------------------
// Launch: hist(0), scan(1), reorder(2), agg(3 <- ncu), gemm_tc(4), ...
// ---------------------------------------------------------------------------
extern "C" void kernel_launch(void* const* d_in, const int* in_sizes, int n_in,
                              void* d_out, int out_size) {
    (void)in_sizes; (void)n_in; (void)out_size;

    const float* x0    = (const float*)d_in[0];
    const int*   ei    = (const int*)d_in[1];      // int32 (JAX x64 disabled)
    const float* Wmsg  = (const float*)d_in[2];    // [3][64][64]
    const float* Wself = (const float*)d_in[3];    // [3][64][64]
    const float* bias  = (const float*)d_in[4];    // [3][64]
    float*       out   = (float*)d_out;

    const int* src = ei;
    const int* dst = ei + N_EDGES;

    float4 *buf0, *buf1, *agg;
    int *cnt, *rowptr, *cursor, *col;
    cudaGetSymbolAddress((void**)&buf0,   g_buf0);
    cudaGetSymbolAddress((void**)&buf1,   g_buf1);
    cudaGetSymbolAddress((void**)&agg,    g_agg);
    cudaGetSymbolAddress((void**)&cnt,    g_cnt);
    cudaGetSymbolAddress((void**)&rowptr, g_rowptr);
    cudaGetSymbolAddress((void**)&cursor, g_cursor);
    cudaGetSymbolAddress((void**)&col,    g_col);

    static bool attr_set = false;
    const int smem_bytes = SMEM_FLOATS * (int)sizeof(float);
    if (!attr_set) {
        cudaFuncSetAttribute(node_gemm_tc_kernel,
                             cudaFuncAttributeMaxDynamicSharedMemorySize, smem_bytes);
        attr_set = true;
    }

    // ---- CSR build ----
    hist_kernel<<<(N_EDGES + 255) / 256, 256>>>(dst, cnt);                      // 0
    scan_kernel<<<1, SCAN_THREADS>>>(cnt, rowptr, cursor);                      // 1
    reorder_kernel<<<(N_EDGES + 255) / 256, 256>>>(src, dst, cursor, col, cnt); // 2

    // ---- Layers ----
    const float* cur[N_LAYERS]  = { x0, (const float*)buf0, (const float*)buf1 };
    float*       next[N_LAYERS] = { (float*)buf0, (float*)buf1, out };

    const int agg_blocks  = (N_NODES + 31) / 32;                    // 1563
    const int gemm_blocks = (N_NODES + TILE_ROWS - 1) / TILE_ROWS;  // 391

    for (int layer = 0; layer < N_LAYERS; layer++) {
        agg_kernel<<<agg_blocks, 256>>>(                            // 3 (layer 0)
            (const float4*)cur[layer], rowptr, col, agg);
        node_gemm_tc_kernel<<<gemm_blocks, 256, smem_bytes>>>(
            cur[layer], (const float*)agg,
            Wself + (size_t)layer * D * D,
            Wmsg  + (size_t)layer * D * D,
            bias  + (size_t)layer * D,
            next[layer],
            layer < N_LAYERS - 1 ? 1 : 0);
    }
}